// round 4
// baseline (speedup 1.0000x reference)
#include <cuda_runtime.h>
#include <cuda_bf16.h>
#include <math.h>
#include <stdint.h>

#define Bn 16
#define Qn 4096
#define Gn 256
#define Cn 80

// ---------------- device scratch (no allocations allowed) ----------------
__device__ float g_tab[(size_t)Bn * Cn * Qn];          // [b][c][q] class cost table (pos-neg)
__device__ unsigned char g_fgm[(size_t)Bn * Qn];       // fg flag per (b,q)
__device__ float g_cost[(size_t)Bn * Gn * Qn];         // [b][g][q]
__device__ int g_rg[(size_t)Bn * Qn];                  // per-row argmin over g
__device__ int g_dk[(size_t)Bn * Gn];                  // dynamic k per column
__device__ int g_sel[(size_t)Bn * Gn * 5];             // top-dk query indices per column
__device__ unsigned g_mb[(size_t)Bn * Qn * 8];         // row bitmasks (256 bits)
__device__ int g_rcnt[(size_t)Bn * Qn];                // row match counts
__device__ int g_pen[(size_t)Bn * Qn];                 // accumulated penalty multiples

// ---------------- helpers ----------------
__device__ __forceinline__ void warpMinPair(float &v, int &i) {
#pragma unroll
    for (int off = 16; off; off >>= 1) {
        float ov = __shfl_xor_sync(0xffffffffu, v, off);
        int   oi = __shfl_xor_sync(0xffffffffu, i, off);
        if (ov < v || (ov == v && oi < i)) { v = ov; i = oi; }
    }
}

// ---------------- K0: class cost table ----------------
__global__ void tab_kernel(const float* __restrict__ logits) {
    int idx = blockIdx.x * 256 + threadIdx.x;   // over B*Q
    if (idx >= Bn * Qn) return;
    int b = idx / Qn, q = idx - b * Qn;
    const float* row = logits + (size_t)idx * Cn;
#pragma unroll 4
    for (int c = 0; c < Cn; c++) {
        float x = row[c];
        float pr = 1.0f / (1.0f + expf(-x));
        float neg = 0.75f * (pr * pr) * (-logf(1.0f - pr + 1e-8f));
        float pos = 0.25f * ((1.0f - pr) * (1.0f - pr)) * (-logf(pr + 1e-8f));
        g_tab[((size_t)b * Cn + c) * Qn + q] = pos - neg;
    }
}

// ---------------- K1: fg mask ----------------
__global__ void fg_kernel(const float* __restrict__ pred_boxes,
                          const float* __restrict__ gt_boxes) {
    __shared__ float s[Gn][8];
    int b = blockIdx.y;
    int q = blockIdx.x * 256 + threadIdx.x;
    int tid = threadIdx.x;
    {
        const float* gb = gt_boxes + ((size_t)b * Gn + tid) * 4;
        float gx0 = gb[0], gy0 = gb[1], gx1 = gb[2], gy1 = gb[3];
        float cx = (gx0 + gx1) * 0.5f, cy = (gy0 + gy1) * 0.5f;
        float gw = gx1 - gx0, gh = gy1 - gy0;
        float x0 = cx - gw * 0.5f, y0 = cy - gh * 0.5f;
        float x1 = cx + gw * 0.5f, y1 = cy + gh * 0.5f;
        float w = x1 - x0, h = y1 - y0;
        s[tid][0] = x0; s[tid][1] = y0; s[tid][2] = x1; s[tid][3] = y1;
        s[tid][4] = cx - 2.5f * w; s[tid][5] = cx + 2.5f * w;
        s[tid][6] = cy - 2.5f * h; s[tid][7] = cy + 2.5f * h;
    }
    __syncthreads();
    float4 p = reinterpret_cast<const float4*>(pred_boxes)[(size_t)b * Qn + q];
    float ax = (p.x + p.z) * 0.5f, ay = (p.y + p.w) * 0.5f;
    unsigned char fg = 0;
    for (int g = 0; g < Gn; g++) {
        bool ib = (ax > s[g][0]) && (ax < s[g][2]) && (ay > s[g][1]) && (ay < s[g][3]);
        bool ic = (ax > s[g][4]) && (ax < s[g][5]) && (ay > s[g][6]) && (ay < s[g][7]);
        if (ib || ic) { fg = 1; break; }
    }
    g_fgm[(size_t)b * Qn + q] = fg;
}

// ---------------- K2: full pairwise cost ----------------
__global__ void cost_kernel(const float* __restrict__ pred_boxes,
                            const float* __restrict__ pred_poses,
                            const int*   __restrict__ labels,
                            const float* __restrict__ gt_boxes,
                            const float* __restrict__ gt_t,
                            const float* __restrict__ gt_r,
                            const float* __restrict__ isz,
                            const float* __restrict__ iszt) {
    int q = blockIdx.x * 256 + threadIdx.x;
    int g = blockIdx.y;
    int b = blockIdx.z;

    const float* gb = gt_boxes + ((size_t)b * Gn + g) * 4;
    float gx0 = gb[0], gy0 = gb[1], gx1 = gb[2], gy1 = gb[3];
    const float* t3 = gt_t + ((size_t)b * Gn + g) * 3;
    const float* r3 = gt_r + ((size_t)b * Gn + g) * 3;
    int lab = labels[b * Gn + g];
    const float* is  = isz + (size_t)b * 4;
    const float* ist = iszt + ((size_t)b * Gn + g) * 4;

    float4 p = reinterpret_cast<const float4*>(pred_boxes)[(size_t)b * Qn + q];
    const float* ps = pred_poses + ((size_t)b * Qn + q) * 6;

    // iou / giou
    float area1 = (p.z - p.x) * (p.w - p.y);
    float area2 = (gx1 - gx0) * (gy1 - gy0);
    float lx = fmaxf(p.x, gx0), ly = fmaxf(p.y, gy0);
    float rx = fminf(p.z, gx1), ry = fminf(p.w, gy1);
    float wx = fmaxf(rx - lx, 0.0f), wy = fmaxf(ry - ly, 0.0f);
    float inter = wx * wy;
    float uni = area1 + area2 - inter;
    float iou = inter / uni;
    float Lx = fminf(p.x, gx0), Ly = fminf(p.y, gy0);
    float Rx = fmaxf(p.z, gx1), Ry = fmaxf(p.w, gy1);
    float ew = fmaxf(Rx - Lx, 0.0f), eh = fmaxf(Ry - Ly, 0.0f);
    float areaE = ew * eh;
    float giou = iou - (areaE - uni) / areaE;

    // l1 bbox (normalized)
    float cb = fabsf(p.x / is[0] - gx0 / ist[0])
             + fabsf(p.y / is[1] - gy0 / ist[1])
             + fabsf(p.z / is[2] - gx1 / ist[2])
             + fabsf(p.w / is[3] - gy1 / ist[3]);

    float cc = g_tab[((size_t)b * Cn + lab) * Qn + q];

    float ct = fabsf(ps[0] - t3[0]) + fabsf(ps[1] - t3[1]) + fabsf(ps[2] - t3[2]);
    float cr = fabsf(ps[3] - r3[0]) + fabsf(ps[4] - r3[1]) + fabsf(ps[5] - r3[2]);

    // in-box / in-ctr (reconstructed gt corners, same round-trip as reference)
    float ax = (p.x + p.z) * 0.5f, ay = (p.y + p.w) * 0.5f;
    float gcx = (gx0 + gx1) * 0.5f, gcy = (gy0 + gy1) * 0.5f;
    float gw = gx1 - gx0, gh = gy1 - gy0;
    float x0 = gcx - gw * 0.5f, y0 = gcy - gh * 0.5f;
    float x1 = gcx + gw * 0.5f, y1 = gcy + gh * 0.5f;
    bool in_box = (ax > x0) && (ax < x1) && (ay > y0) && (ay < y1);
    float w = x1 - x0, h = y1 - y0;
    bool in_ctr = (ax > gcx - 2.5f * w) && (ax < gcx + 2.5f * w) &&
                  (ay > gcy - 2.5f * h) && (ay < gcy + 2.5f * h);
    bool both = in_box && in_ctr;

    float cost = 5.0f * cb + 2.0f * cc + 2.0f * (-giou)
               + 100.0f * (both ? 0.0f : 1.0f) + 1.0f * ct + 1.0f * cr;
    cost += g_fgm[(size_t)b * Qn + q] ? 0.0f : 10000.0f;

    g_cost[((size_t)b * Gn + g) * Qn + q] = cost;
}

// ---------------- K3: per-row argmin over g (coalesced) ----------------
__global__ void rowmin_kernel() {
    int b = blockIdx.y;
    int q = blockIdx.x * 256 + threadIdx.x;
    const float* Cb = g_cost + (size_t)b * Gn * Qn;
    float bv = INFINITY; int bg = 0;
    for (int g = 0; g < Gn; g++) {
        float v = Cb[(size_t)g * Qn + q];
        if (v < bv) { bv = v; bg = g; }
    }
    g_rg[(size_t)b * Qn + q] = bg;
}

// ---------------- K4: per-column dk (iou top5 sum) + stable cost top-dk ----------------
__global__ void topk_kernel(const float* __restrict__ pred_boxes,
                            const float* __restrict__ gt_boxes) {
    int warp = threadIdx.x >> 5, lane = threadIdx.x & 31;
    int g = blockIdx.x * 4 + warp;
    int b = blockIdx.y;
    const float4* pb = reinterpret_cast<const float4*>(pred_boxes) + (size_t)b * Qn;
    const float* gb = gt_boxes + ((size_t)b * Gn + g) * 4;
    float gx0 = gb[0], gy0 = gb[1], gx1 = gb[2], gy1 = gb[3];
    float area2 = (gx1 - gx0) * (gy1 - gy0);
    const float* col = g_cost + ((size_t)b * Gn + g) * Qn;

    float iv[5]; float cv[5]; int ci[5];
#pragma unroll
    for (int k = 0; k < 5; k++) { iv[k] = -INFINITY; cv[k] = INFINITY; ci[k] = 0x7fffffff; }

    for (int q = lane; q < Qn; q += 32) {
        float4 p = pb[q];
        float a1 = (p.z - p.x) * (p.w - p.y);
        float lx = fmaxf(p.x, gx0), ly = fmaxf(p.y, gy0);
        float rx = fminf(p.z, gx1), ry = fminf(p.w, gy1);
        float wx = fmaxf(rx - lx, 0.0f), wy = fmaxf(ry - ly, 0.0f);
        float inter = wx * wy;
        float iou = inter / (a1 + area2 - inter);
        if (iou > iv[4]) {
            iv[4] = iou;
#pragma unroll
            for (int k = 4; k > 0; k--)
                if (iv[k] > iv[k - 1]) { float t = iv[k]; iv[k] = iv[k - 1]; iv[k - 1] = t; }
        }
        float c = col[q];
        if (c < cv[4] || (c == cv[4] && q < ci[4])) {
            cv[4] = c; ci[4] = q;
#pragma unroll
            for (int k = 4; k > 0; k--)
                if (cv[k] < cv[k - 1] || (cv[k] == cv[k - 1] && ci[k] < ci[k - 1])) {
                    float tv = cv[k]; cv[k] = cv[k - 1]; cv[k - 1] = tv;
                    int ti = ci[k]; ci[k] = ci[k - 1]; ci[k - 1] = ti;
                }
        }
    }

    // merge: iou top-5 sum (descending order, matches topk.sum(-1))
    int p5 = 0; float sum = 0.0f;
    for (int r = 0; r < 5; r++) {
        float cand = (p5 < 5) ? iv[p5] : -INFINITY;
        float m = cand;
#pragma unroll
        for (int off = 16; off; off >>= 1) m = fmaxf(m, __shfl_xor_sync(0xffffffffu, m, off));
        sum += m;
        unsigned ball = __ballot_sync(0xffffffffu, cand == m);
        if (lane == (__ffs(ball) - 1)) p5++;
    }
    int dk = (int)sum;
    if (dk < 1) dk = 1;
    if (dk > 5) dk = 5;

    // merge: cost (value, idx) lexicographic top-5, write first dk
    int p2 = 0;
    for (int r = 0; r < 5; r++) {
        float cand = (p2 < 5) ? cv[p2] : INFINITY;
        int candi = (p2 < 5) ? ci[p2] : 0x7fffffff;
        float mv = cand; int mi = candi;
        warpMinPair(mv, mi);
        unsigned ball = __ballot_sync(0xffffffffu, (cand == mv) && (candi == mi));
        if (lane == (__ffs(ball) - 1)) p2++;
        if (lane == 0 && r < dk) g_sel[((size_t)b * Gn + g) * 5 + r] = mi;
    }
    if (lane == 0) g_dk[(size_t)b * Gn + g] = dk;
}

// ---------------- K5: sequential matching, one block per batch ----------------
__device__ __forceinline__ void reset_row(unsigned* mb, int* rcnt, int* s_col, int q, int r) {
#pragma unroll
    for (int w = 0; w < 8; w++) {
        unsigned bits = mb[q * 8 + w];
        unsigned keep = ((r >> 5) == w) ? (1u << (r & 31)) : 0u;
        unsigned clr = bits & ~keep;
        while (clr) {
            int gp = __ffs(clr) - 1; clr &= clr - 1;
            atomicSub(&s_col[w * 32 + gp], 1);
        }
        if (keep && !(bits & keep)) atomicAdd(&s_col[r], 1);
        mb[q * 8 + w] = keep;
    }
    rcnt[q] = 1;
}

__global__ void __launch_bounds__(1024, 1) match_kernel(float* __restrict__ out) {
    int b = blockIdx.x, tid = threadIdx.x;
    const float* Cb = g_cost + (size_t)b * Gn * Qn;
    unsigned* mb = g_mb + (size_t)b * Qn * 8;
    int* rcnt = g_rcnt + (size_t)b * Qn;
    int* pen  = g_pen  + (size_t)b * Qn;
    const int* rg = g_rg + (size_t)b * Qn;

    __shared__ int s_col[Gn];
    __shared__ unsigned s_stale[Qn / 32];
    __shared__ int s_un[Gn];
    __shared__ int s_ucnt, s_conf;

    for (int i = tid; i < Qn * 8; i += 1024) mb[i] = 0u;
    for (int i = tid; i < Qn; i += 1024) { rcnt[i] = 0; pen[i] = 0; }
    for (int g = tid; g < Gn; g += 1024) s_col[g] = g_dk[b * Gn + g];
    for (int w = tid; w < Qn / 32; w += 1024) s_stale[w] = 0u;
    __syncthreads();

    // initial m from per-column top-dk
    for (int g = tid; g < Gn; g += 1024) {
        int dk = g_dk[b * Gn + g];
        for (int j = 0; j < dk; j++) {
            int q = g_sel[((size_t)b * Gn + g) * 5 + j];
            atomicOr(&mb[q * 8 + (g >> 5)], 1u << (g & 31));
            atomicAdd(&rcnt[q], 1);
        }
    }
    __syncthreads();
    // stale set (original, fixed for the whole loop)
    for (int q = tid; q < Qn; q += 1024)
        if (rcnt[q] > 1) atomicOr(&s_stale[q >> 5], 1u << (q & 31));
    __syncthreads();
    for (int q = tid; q < Qn; q += 1024)
        if ((s_stale[q >> 5] >> (q & 31)) & 1) reset_row(mb, rcnt, s_col, q, rg[q]);
    __syncthreads();

    int wid = tid >> 5, lane = tid & 31;
    for (int it = 0; it < Gn; it++) {
        if (tid == 0) { s_ucnt = 0; s_conf = 0; }
        __syncthreads();
        for (int g = tid; g < Gn; g += 1024)
            if (s_col[g] == 0) { int k = atomicAdd(&s_ucnt, 1); s_un[k] = g; }
        __syncthreads();
        if (s_ucnt == 0) break;   // fixed point, matches fori_loop freeze
        // this is a "needed" iteration: accumulate row penalties
        for (int q = tid; q < Qn; q += 1024) if (rcnt[q] > 0) pen[q]++;
        __syncthreads();
        int nu = s_ucnt;
        for (int u = wid; u < nu; u += 32) {
            int g = s_un[u];
            const float* col = Cb + (size_t)g * Qn;
            float bv = INFINITY; int bi = 0;
            for (int q = lane; q < Qn; q += 32) {
                float v = col[q] + 100000.0f * (float)pen[q];
                if (v < bv) { bv = v; bi = q; }
            }
            warpMinPair(bv, bi);
            if (lane == 0) {
                atomicOr(&mb[bi * 8 + (g >> 5)], 1u << (g & 31));
                atomicAdd(&rcnt[bi], 1);
                s_col[g] = 1;
            }
        }
        __syncthreads();
        for (int q = tid; q < Qn; q += 1024) if (rcnt[q] > 1) s_conf = 1;
        __syncthreads();
        if (s_conf) {
            for (int q = tid; q < Qn; q += 1024)
                if ((s_stale[q >> 5] >> (q & 31)) & 1) reset_row(mb, rcnt, s_col, q, rg[q]);
            __syncthreads();
        }
    }

    // ---------- outputs (float32!) ----------
    float* out_sel = out;
    float* out_gt  = out + Bn * Qn;
    float* out_mq  = out + 2 * Bn * Qn;
    for (int q = tid; q < Qn; q += 1024) {
        out_sel[(size_t)b * Qn + q] = (rcnt[q] > 0) ? 1.0f : 0.0f;
        int first = 0;
#pragma unroll
        for (int w = 7; w >= 0; w--) {
            unsigned bits = mb[q * 8 + w];
            if (bits) first = w * 32 + __ffs(bits) - 1;
        }
        out_gt[(size_t)b * Qn + q] = (float)first;
    }
    __syncthreads();
    for (int g = wid; g < Gn; g += 32) {
        const float* col = Cb + (size_t)g * Qn;
        int wsel = g >> 5; unsigned bsel = 1u << (g & 31);
        float bv = INFINITY; int bi = 0;
        for (int q = lane; q < Qn; q += 32) {
            if (mb[q * 8 + wsel] & bsel) {
                float v = col[q];
                int p = pen[q];
                for (int k = 0; k < p; k++) v += 100000.0f;  // replicate sequential fp accumulation
                if (v < bv) { bv = v; bi = q; }
            }
        }
        warpMinPair(bv, bi);
        if (lane == 0) out_mq[(size_t)b * Gn + g] = (float)bi;
    }
}

// ---------------- launch ----------------
extern "C" void kernel_launch(void* const* d_in, const int* in_sizes, int n_in,
                              void* d_out, int out_size) {
    const float* pred_logits = (const float*)d_in[0];
    const float* pred_boxes  = (const float*)d_in[1];
    const float* pred_poses  = (const float*)d_in[2];
    const int*   labels      = (const int*)  d_in[3];
    const float* gt_boxes    = (const float*)d_in[4];
    const float* gt_trans    = (const float*)d_in[5];
    const float* gt_rot      = (const float*)d_in[6];
    const float* isz         = (const float*)d_in[7];
    const float* iszt        = (const float*)d_in[8];
    float* out = (float*)d_out;

    tab_kernel<<<(Bn * Qn + 255) / 256, 256>>>(pred_logits);
    fg_kernel<<<dim3(Qn / 256, Bn), 256>>>(pred_boxes, gt_boxes);
    cost_kernel<<<dim3(Qn / 256, Gn, Bn), 256>>>(pred_boxes, pred_poses, labels,
                                                 gt_boxes, gt_trans, gt_rot, isz, iszt);
    rowmin_kernel<<<dim3(Qn / 256, Bn), 256>>>();
    topk_kernel<<<dim3(Gn / 4, Bn), 128>>>(pred_boxes, gt_boxes);
    match_kernel<<<Bn, 1024>>>(out);
}